// round 15
// baseline (speedup 1.0000x reference)
#include <cuda_runtime.h>

// AtteMatchLay: multi-perspective cosine similarity.
// out[n][p] = dot / (max(sqrt(n1),eps) * max(sqrt(n2),eps))
//   dot = sum_d r*m*w2, n1 = sum_d r^2*w2, n2 = sum_d m^2*w2, w2 = weight^2
// N = 8192, D = 768, P = 20. fp32.
//
// R15: DRAM-latency hiding. R7 vs R14 proved no pipe is binding (different
// L1 loads, identical time; issue ~34-40%) -> LDG latency-bound at 16
// warps/SM. Fix: cp.async (LDGSTS) 4-stage ring stages r/m chunks into
// shared 3 stages ahead (zero register cost in flight); compute consumes
// via 29-cyc LDS. Both p-groups share the staged data -> no duplicate DRAM
// reads. Compute core = R14: 2 rows/thread, p-split (warps 0-3: p0..11,
// warps 4-7: p12..19), R7 block-local w2 swizzle.

#define DD 768
#define PP 20
#define BLKB 2688          // bytes per 32-d w2 swizzle block
#define THREADS 256
#define NSTAGE 4
#define STAGEB 8192        // 2 mats x 32 rows x 32 d x 4B
#define HALF   4096        // r part / m part within a stage

typedef unsigned long long u64;

__device__ __forceinline__ int w2t_off(int d) {
    int b = d >> 5;
    int dl = d & 31;
    return b * BLKB + dl * 80 + ((dl >> 2) & 7) * 16;
}
__device__ __forceinline__ u64 pack2(float x) {
    u64 r; asm("mov.b64 %0, {%1, %1};" : "=l"(r) : "f"(x)); return r;
}
__device__ __forceinline__ float2 unpack2(u64 v) {
    float2 f; asm("mov.b64 {%0, %1}, %2;" : "=f"(f.x), "=f"(f.y) : "l"(v)); return f;
}
__device__ __forceinline__ void fma2(u64& d, u64 a, u64 b) {
    asm("fma.rn.f32x2 %0, %1, %2, %0;" : "+l"(d) : "l"(a), "l"(b));
}
__device__ __forceinline__ u64 mul2(u64 a, u64 b) {
    u64 r; asm("mul.rn.f32x2 %0, %1, %2;" : "=l"(r) : "l"(a), "l"(b)); return r;
}
__device__ __forceinline__ unsigned smem_u32(const void* p) {
    return (unsigned)__cvta_generic_to_shared(p);
}
__device__ __forceinline__ void cp16(unsigned dst, const void* src) {
    asm volatile("cp.async.cg.shared.global [%0], [%1], 16;"
                 :: "r"(dst), "l"(src));
}
__device__ __forceinline__ void cp_commit() {
    asm volatile("cp.async.commit_group;");
}
__device__ __forceinline__ void cp_wait2() {
    asm volatile("cp.async.wait_group 2;");
}

// Issue one stage's loads: 512 x 16B chunks, 2 per thread.
// chunk c: half = c>>8 (0=r,1=m), row = (c&255)>>3, dg = c&7.
__device__ __forceinline__ void issue_stage(
    unsigned sbase, const float* __restrict__ repres,
    const float* __restrict__ max_att, int row0, int iter, int tid)
{
#pragma unroll
    for (int q = 0; q < 2; q++) {
        int c    = tid * 2 + q;
        int half = c >> 8;
        int row  = (c & 255) >> 3;
        int dg   = c & 7;
        const float* src = (half ? max_att : repres)
                         + (size_t)(row0 + row) * DD + iter * 32 + dg * 4;
        cp16(sbase + half * HALF + row * 128 + dg * 16, src);
    }
    cp_commit();
}

extern "C" __global__ void __launch_bounds__(THREADS, 2)
atte_matchlay_kernel(const float* __restrict__ repres,
                     const float* __restrict__ max_att,
                     const float* __restrict__ weight,
                     float* __restrict__ out, int nrows)
{
    extern __shared__ char smem[];
    char* w2t = smem;                              // 64512 B, swizzled
    char* rbuf = smem + (DD / 32) * BLKB;          // NSTAGE x 8192 B

    for (int idx = threadIdx.x; idx < PP * DD; idx += THREADS) {
        int p = idx / DD;
        int d = idx - p * DD;
        float w = weight[idx];
        *(float*)(w2t + w2t_off(d) + p * 4) = w * w;
    }

    const int tid  = threadIdx.x;
    const int warp = tid >> 5;
    const int lane = tid & 31;
    const int pg   = warp >> 2;   // 0: p0..11, 1: p12..19
    const int rw   = warp & 3;
    const int rg   = lane >> 3;
    const int dl   = lane & 7;
    const int row0 = blockIdx.x * 32;                 // block rows
    const int lrow = rw * 8 + rg * 2;                 // local row (0..30, even)
    const int row  = row0 + lrow;

    const unsigned rbase = smem_u32(rbuf);

    // Prologue: issue stages 0,1,2
#pragma unroll
    for (int s = 0; s < NSTAGE - 1; s++)
        issue_stage(rbase + s * STAGEB, repres, max_att, row0, s, tid);

    __syncthreads();  // w2t ready (cp.async completion handled by wait_group)

    const int NP   = (pg == 0) ? 6 : 4;   // f32x2 pairs this group
    const int POFF = (pg == 0) ? 0 : 48;  // byte offset into w2 row

    // accumulators (max footprint for pg0; pg1 uses first 4)
    u64 aD[2][6], aN1[2][6], aN2[2][6];
#pragma unroll
    for (int t = 0; t < 2; t++)
#pragma unroll
        for (int k = 0; k < 6; k++) {
            aD[t][k] = 0ull; aN1[t][k] = 0ull; aN2[t][k] = 0ull;
        }

    for (int i = 0; i < 24; i++) {
        cp_wait2();         // stage i complete
        __syncthreads();    // all warps see it

        // issue stage i+3 (clamped re-issue keeps group-count invariant)
        int nxt = i + NSTAGE - 1;
        int nc  = nxt < 24 ? nxt : 23;
        issue_stage(rbase + (nxt & (NSTAGE - 1)) * STAGEB,
                    repres, max_att, row0, nc, tid);

        const char* stg = rbuf + (i & (NSTAGE - 1)) * STAGEB;
        float4 rA = *(const float4*)(stg + lrow * 128 + dl * 16);
        float4 rB = *(const float4*)(stg + (lrow + 1) * 128 + dl * 16);
        float4 mA = *(const float4*)(stg + HALF + lrow * 128 + dl * 16);
        float4 mB = *(const float4*)(stg + HALF + (lrow + 1) * 128 + dl * 16);

        const int d0 = i * 32 + dl * 4;
        float rvA[4] = {rA.x, rA.y, rA.z, rA.w};
        float mvA[4] = {mA.x, mA.y, mA.z, mA.w};
        float rvB[4] = {rB.x, rB.y, rB.z, rB.w};
        float mvB[4] = {mB.x, mB.y, mB.z, mB.w};

#pragma unroll
        for (int j = 0; j < 4; j++) {
            const char* base = w2t + w2t_off(d0 + j) + POFF;
            u64 wv[6];
            {
                ulonglong2 w0 = *(const ulonglong2*)(base);
                ulonglong2 w1 = *(const ulonglong2*)(base + 16);
                wv[0] = w0.x; wv[1] = w0.y; wv[2] = w1.x; wv[3] = w1.y;
            }
            if (pg == 0) {
                ulonglong2 w2_ = *(const ulonglong2*)(base + 32);
                wv[4] = w2_.x; wv[5] = w2_.y;
            }

            u64 r2A = pack2(rvA[j]), m2A = pack2(mvA[j]);
            u64 rmA = mul2(r2A, m2A), rrA = mul2(r2A, r2A), mmA = mul2(m2A, m2A);
            u64 r2B = pack2(rvB[j]), m2B = pack2(mvB[j]);
            u64 rmB = mul2(r2B, m2B), rrB = mul2(r2B, r2B), mmB = mul2(m2B, m2B);

#pragma unroll
            for (int k = 0; k < 6; k++) {
                if (k < NP) {
                    fma2(aD[0][k],  rmA, wv[k]);
                    fma2(aN1[0][k], rrA, wv[k]);
                    fma2(aN2[0][k], mmA, wv[k]);
                    fma2(aD[1][k],  rmB, wv[k]);
                    fma2(aN1[1][k], rrB, wv[k]);
                    fma2(aN2[1][k], mmB, wv[k]);
                }
            }
        }
        __syncthreads();    // stage i consumed before slot reuse
    }

    const int NPF   = 2 * NP;
    const float EPS = 1e-8f;
    const int PBASE = POFF / 4;

#pragma unroll
    for (int t = 0; t < 2; t++) {
        float dot[12], n1[12], n2[12];
#pragma unroll
        for (int k = 0; k < 6; k++) {
            float2 a = unpack2(aD[t][k]);  dot[2*k] = a.x; dot[2*k+1] = a.y;
            float2 b = unpack2(aN1[t][k]); n1[2*k]  = b.x; n1[2*k+1]  = b.y;
            float2 c = unpack2(aN2[t][k]); n2[2*k]  = c.x; n2[2*k+1]  = c.y;
        }
#pragma unroll
        for (int p = 0; p < 12; p++) {
            if (p < NPF) {
#pragma unroll
                for (int o = 1; o < 8; o <<= 1) {
                    dot[p] += __shfl_xor_sync(0xffffffffu, dot[p], o);
                    n1[p]  += __shfl_xor_sync(0xffffffffu, n1[p],  o);
                    n2[p]  += __shfl_xor_sync(0xffffffffu, n2[p],  o);
                }
            }
        }
#pragma unroll
        for (int p0 = 0; p0 < 12; p0 += 8) {
            int p = p0 + dl;
            if (p < NPF) {
                float a = fmaxf(sqrtf(n1[p]), EPS);
                float b = fmaxf(sqrtf(n2[p]), EPS);
                out[(size_t)(row + t) * PP + PBASE + p] = dot[p] / (a * b);
            }
        }
    }
}

extern "C" void kernel_launch(void* const* d_in, const int* in_sizes, int n_in,
                              void* d_out, int out_size) {
    const float* repres  = (const float*)d_in[0];
    const float* max_att = (const float*)d_in[1];
    const float* weight  = (const float*)d_in[2];
    float* out = (float*)d_out;

    int nrows = in_sizes[0] / DD;                       // 8192
    int smem  = (DD / 32) * BLKB + NSTAGE * STAGEB;     // 64512 + 32768 = 97280

    cudaFuncSetAttribute(atte_matchlay_kernel,
                         cudaFuncAttributeMaxDynamicSharedMemorySize, smem);

    int grid = (nrows + 31) / 32;                       // 256
    atte_matchlay_kernel<<<grid, THREADS, smem>>>(repres, max_att, weight, out, nrows);
}